// round 1
// baseline (speedup 1.0000x reference)
#include <cuda_runtime.h>
#include <cuda_fp16.h>

#define TT 256
#define CC 56
#define HH 1024
#define NBLK 128
#define NTHR 256
#define NWARP (NBLK*(NTHR/32))   /* 1024 == HH: one gate-quadruple per warp */

// ---------------- fp16 weight copies (filled by convert_kernel each launch) ----
__device__ __half s_Wih_mid[(size_t)4*4096*2048];
__device__ __half s_Whh_mid[(size_t)4*4096*1024];
__device__ __half s_Wih_top[(size_t)4096*1024];
__device__ __half s_Whh_top[(size_t)4096*1024];
__device__ __half s_Wmid[(size_t)4*1024*1024];
__device__ __half s_Vmid[(size_t)4*1024*1024];
__device__ __half s_V1[(size_t)56*1024];
__device__ __half s_W0[(size_t)1024*56];

// ---------------- activation / carry scratch ----------------------------------
__device__ float g_h[2][5][HH];      // double-buffered hidden state (parity = t&1)
__device__ float g_c[5][HH];         // cell state (owner-warp only)
__device__ float g_TD[4][HH];        // TD error per mid layer (carry)
__device__ float g_reconR[4][HH];    // recon from layers 2..5 (carry)
__device__ float g_recon1[CC];       // recon from layer 1 (carry)
__device__ float g_BU[HH];           // bottom-up input to next LSTM
__device__ float g_loss_parts[TT][5];

__device__ unsigned g_bar_count = 0;
__device__ unsigned g_bar_gen   = 0;

// ---------------- helpers -----------------------------------------------------
__device__ __forceinline__ float ldf(const float* p) { return __ldcg(p); }
__device__ __forceinline__ void  stf(float* p, float v) { __stcg(p, v); }

__device__ __forceinline__ float warp_red(float v) {
#pragma unroll
    for (int o = 16; o; o >>= 1) v += __shfl_xor_sync(0xffffffffu, v, o);
    return v;
}

// lane-partial dot: fp16 weights (global), fp32 x (smem). n multiple of 128.
__device__ __forceinline__ float dot_part(const __half* __restrict__ w,
                                          const float* __restrict__ x,
                                          int n, int lane) {
    float acc = 0.f;
#pragma unroll 4
    for (int c = lane * 4; c < n; c += 128) {
        uint2 wr = *reinterpret_cast<const uint2*>(w + c);
        __half2 h0 = *reinterpret_cast<const __half2*>(&wr.x);
        __half2 h1 = *reinterpret_cast<const __half2*>(&wr.y);
        float2 f0 = __half22float2(h0);
        float2 f1 = __half22float2(h1);
        float4 xv = *reinterpret_cast<const float4*>(x + c);
        acc = fmaf(f0.x, xv.x, acc);
        acc = fmaf(f0.y, xv.y, acc);
        acc = fmaf(f1.x, xv.z, acc);
        acc = fmaf(f1.y, xv.w, acc);
    }
    return acc;
}

// lane-partial dot over 56 elements (W0 rows)
__device__ __forceinline__ float dot56(const __half* __restrict__ w,
                                       const float* __restrict__ x, int lane) {
    float acc = 0.f;
    if (lane < 28) {
        __half2 h = *reinterpret_cast<const __half2*>(w + lane * 2);
        float2 f = __half22float2(h);
        acc = f.x * x[lane * 2] + f.y * x[lane * 2 + 1];
    }
    return acc;
}

__device__ __forceinline__ void gsync() {
    __threadfence();
    __syncthreads();
    if (threadIdx.x == 0) {
        volatile unsigned* genp = &g_bar_gen;
        unsigned gen = *genp;
        unsigned prev = atomicAdd(&g_bar_count, 1u);
        if (prev == NBLK - 1) {
            atomicSub(&g_bar_count, (unsigned)NBLK);
            __threadfence();
            *genp = gen + 1u;
        } else {
            while (*genp == gen) { }
        }
    }
    __syncthreads();
}

__device__ __forceinline__ float block_sum(float v, float* sred) {
    int lane = threadIdx.x & 31, w = threadIdx.x >> 5;
    v = warp_red(v);
    if (lane == 0) sred[w] = v;
    __syncthreads();
    float r = 0.f;
    if (w == 0) {
        r = (lane < NTHR / 32) ? sred[lane] : 0.f;
        r = warp_red(r);
    }
    __syncthreads();
    return r;   // valid in warp 0
}

__device__ __forceinline__ float sigm(float x) { return 1.f / (1.f + __expf(-x)); }

// ---------------- conversion pre-pass ------------------------------------------
__global__ void convert_kernel(const float* __restrict__ W0, const float* __restrict__ Wmid,
                               const float* __restrict__ V1, const float* __restrict__ Vmid,
                               const float* __restrict__ Wihm, const float* __restrict__ Whhm,
                               const float* __restrict__ Wiht, const float* __restrict__ Whht) {
    long i0 = (long)blockIdx.x * blockDim.x + threadIdx.x;
    long st = (long)gridDim.x * blockDim.x;
#define CVT(dst, src, n)                                                       \
    for (long i = i0; i < (long)(n) / 2; i += st)                              \
        ((__half2*)(dst))[i] = __float22half2_rn(((const float2*)(src))[i]);
    CVT(s_Wih_mid, Wihm, 4L * 4096 * 2048)
    CVT(s_Whh_mid, Whhm, 4L * 4096 * 1024)
    CVT(s_Wih_top, Wiht, 4096L * 1024)
    CVT(s_Whh_top, Whht, 4096L * 1024)
    CVT(s_Wmid, Wmid, 4L * 1024 * 1024)
    CVT(s_Vmid, Vmid, 4L * 1024 * 1024)
    CVT(s_V1, V1, 56L * 1024)
    CVT(s_W0, W0, 1024L * 56)
#undef CVT
}

// ---------------- main persistent kernel ----------------------------------------
__global__ void __launch_bounds__(NTHR, 1)
predcells_kernel(const float* __restrict__ x_seq,
                 const float* __restrict__ W0_b,  const float* __restrict__ Wmid_b,
                 const float* __restrict__ V1_b,  const float* __restrict__ Vmid_b,
                 const float* __restrict__ bmid,  const float* __restrict__ btop,
                 float* __restrict__ out) {
    __shared__ float sx[2 * HH];
    __shared__ float sh[HH];
    __shared__ float saux[HH];
    __shared__ float sred[32];

    const int tid  = threadIdx.x;
    const int lane = tid & 31;
    const int wid  = tid >> 5;
    const int gw   = blockIdx.x * (NTHR / 32) + wid;
    const long gtid = (long)blockIdx.x * NTHR + tid;
    const long gsz  = (long)NBLK * NTHR;

    // ---- prologue: zero carries, BU0 for t=0, loss0(t=0) ----
    for (long i = gtid; i < 5 * HH; i += gsz) { int l = (int)(i / HH), k = (int)(i % HH); g_h[0][l][k] = 0.f; g_c[l][k] = 0.f; }
    for (long i = gtid; i < 4 * HH; i += gsz) { int l = (int)(i / HH), k = (int)(i % HH); g_TD[l][k] = 0.f; g_reconR[l][k] = 0.f; }
    for (long i = gtid; i < CC; i += gsz) g_recon1[i] = 0.f;
    for (int i = tid; i < CC; i += NTHR) saux[i] = fabsf(x_seq[i]);   // TD0(t=0) = |x_0|
    __syncthreads();
    for (int task = gw; task < HH; task += NWARP) {
        float a = warp_red(dot56(&s_W0[(size_t)task * CC], saux, lane));
        if (lane == 0) stf(&g_BU[task], a + W0_b[task]);
    }
    if (blockIdx.x == 0) {
        float s = block_sum((tid < CC) ? saux[tid] : 0.f, sred);
        if (tid == 0) stf(&g_loss_parts[0][0], s);
    }
    gsync();

    for (int t = 0; t < TT; t++) {
        const int p = t & 1;

#pragma unroll 1
        for (int m = 0; m < 4; m++) {
            // ---- LSTM mid layer m:  x = [BU ; TD[m]],  h = g_h[p][m] ----
            for (int i = tid; i < HH; i += NTHR) {
                sx[i]      = ldf(&g_BU[i]);
                sx[HH + i] = ldf(&g_TD[m][i]);
                sh[i]      = ldf(&g_h[p][m][i]);
            }
            __syncthreads();
            {
                const int k = gw;   // NWARP == HH
                const __half* wih = &s_Wih_mid[(size_t)m * 4096 * 2048];
                const __half* whh = &s_Whh_mid[(size_t)m * 4096 * 1024];
                float z[4];
#pragma unroll
                for (int q = 0; q < 4; q++) {
                    int row = q * HH + k;
                    float a = dot_part(wih + (size_t)row * 2048, sx, 2048, lane)
                            + dot_part(whh + (size_t)row * 1024, sh, 1024, lane);
                    z[q] = warp_red(a) + bmid[m * 4096 + row];
                }
                if (lane == 0) {
                    float ig = sigm(z[0]), fg = sigm(z[1]);
                    float gg = tanhf(z[2]), og = sigm(z[3]);
                    float cn = fg * ldf(&g_c[m][k]) + ig * gg;
                    stf(&g_c[m][k], cn);
                    stf(&g_h[1 - p][m][k], og * tanhf(cn));
                }
            }
            gsync();

            // ---- X phase m: TD[m]=|h_new - reconR[m]|, recon, BU = Wmid@TD ----
            for (int i = tid; i < HH; i += NTHR) {
                float hn = ldf(&g_h[1 - p][m][i]);
                sh[i]   = hn;
                saux[i] = fabsf(hn - ldf(&g_reconR[m][i]));
            }
            __syncthreads();
            const int nrec = (m == 0) ? CC : HH;
            for (int task = gw; task < HH + nrec; task += NWARP) {
                if (task < HH) {
                    float a = warp_red(dot_part(&s_Wmid[((size_t)m * HH + task) * HH], saux, HH, lane));
                    if (lane == 0) stf(&g_BU[task], a + Wmid_b[m * HH + task]);
                } else {
                    int r = task - HH;
                    if (m == 0) {
                        float a = warp_red(dot_part(&s_V1[(size_t)r * HH], sh, HH, lane));
                        if (lane == 0) stf(&g_recon1[r], a + V1_b[r]);
                    } else {
                        float a = warp_red(dot_part(&s_Vmid[((size_t)(m - 1) * HH + r) * HH], sh, HH, lane));
                        if (lane == 0) stf(&g_reconR[m - 1][r], a + Vmid_b[(m - 1) * HH + r]);
                    }
                }
            }
            if (blockIdx.x == 0) {
                float v = 0.f;
                for (int i = tid; i < HH; i += NTHR) { stf(&g_TD[m][i], saux[i]); v += saux[i]; }
                float s = block_sum(v, sred);
                if (tid == 0) stf(&g_loss_parts[t][1 + m], s);
            }
            gsync();
        }

        // ---- top LSTM: x = BU only ----
        for (int i = tid; i < HH; i += NTHR) {
            sx[i] = ldf(&g_BU[i]);
            sh[i] = ldf(&g_h[p][4][i]);
        }
        __syncthreads();
        {
            const int k = gw;
            float z[4];
#pragma unroll
            for (int q = 0; q < 4; q++) {
                int row = q * HH + k;
                float a = dot_part(&s_Wih_top[(size_t)row * 1024], sx, 1024, lane)
                        + dot_part(&s_Whh_top[(size_t)row * 1024], sh, 1024, lane);
                z[q] = warp_red(a) + btop[row];
            }
            if (lane == 0) {
                float ig = sigm(z[0]), fg = sigm(z[1]);
                float gg = tanhf(z[2]), og = sigm(z[3]);
                float cn = fg * ldf(&g_c[4][k]) + ig * gg;
                stf(&g_c[4][k], cn);
                stf(&g_h[1 - p][4][k], og * tanhf(cn));
            }
        }
        gsync();

        // ---- X5: recon_top = Vmid[3]@h_top; fused BU0/loss0 for step t+1 ----
        {
            const bool more = (t + 1 < TT);
            for (int i = tid; i < HH; i += NTHR) sh[i] = ldf(&g_h[1 - p][4][i]);
            if (more)
                for (int i = tid; i < CC; i += NTHR)
                    saux[i] = fabsf(x_seq[(t + 1) * CC + i] - ldf(&g_recon1[i]));
            __syncthreads();
            const int ntask = HH + (more ? HH : 0);
            for (int task = gw; task < ntask; task += NWARP) {
                if (task < HH) {
                    float a = warp_red(dot_part(&s_Vmid[((size_t)3 * HH + task) * HH], sh, HH, lane));
                    if (lane == 0) stf(&g_reconR[3][task], a + Vmid_b[3 * HH + task]);
                } else {
                    int r = task - HH;
                    float a = warp_red(dot56(&s_W0[(size_t)r * CC], saux, lane));
                    if (lane == 0) stf(&g_BU[r], a + W0_b[r]);
                }
            }
            if (more && blockIdx.x == 0) {
                float s = block_sum((tid < CC) ? saux[tid] : 0.f, sred);
                if (tid == 0) stf(&g_loss_parts[t + 1][0], s);
            }
        }
        gsync();
    }

    // ---- epilogue: deterministic reduction of loss parts ----
    if (blockIdx.x == 0) {
        const float* parts = &g_loss_parts[0][0];
        float v = 0.f;
        for (int i = tid; i < TT * 5; i += NTHR) v += ldf(&parts[i]);
        float s = block_sum(v, sred);
        if (tid == 0) out[0] = s;
    }
}

// ---------------- launch ---------------------------------------------------------
extern "C" void kernel_launch(void* const* d_in, const int* in_sizes, int n_in,
                              void* d_out, int out_size) {
    (void)in_sizes; (void)n_in; (void)out_size;
    const float* x_seq  = (const float*)d_in[0];
    const float* W0_w   = (const float*)d_in[1];
    const float* W0_b   = (const float*)d_in[2];
    const float* Wmid_w = (const float*)d_in[3];
    const float* Wmid_b = (const float*)d_in[4];
    const float* V1_w   = (const float*)d_in[5];
    const float* V1_b   = (const float*)d_in[6];
    const float* Vmid_w = (const float*)d_in[7];
    const float* Vmid_b = (const float*)d_in[8];
    const float* Wihm   = (const float*)d_in[9];
    const float* Whhm   = (const float*)d_in[10];
    const float* bmid   = (const float*)d_in[11];
    const float* Wiht   = (const float*)d_in[12];
    const float* Whht   = (const float*)d_in[13];
    const float* btop   = (const float*)d_in[14];

    convert_kernel<<<2048, 256>>>(W0_w, Wmid_w, V1_w, Vmid_w, Wihm, Whhm, Wiht, Whht);
    predcells_kernel<<<NBLK, NTHR>>>(x_seq, W0_b, Wmid_b, V1_b, Vmid_b, bmid, btop,
                                     (float*)d_out);
}

// round 2
// speedup vs baseline: 1.1190x; 1.1190x over previous
#include <cuda_runtime.h>
#include <cuda_fp16.h>
#include <cuda_fp8.h>

#define TT 256
#define CC 56
#define HH 1024
#define NBLK 148
#define NTHR 1024
#define INV_WSCALE (1.0f/64.0f)

// ---------------- quantized weights (filled by convert_kernel each launch) ----
__device__ __align__(16) unsigned char w8_Wih_mid[(size_t)4*4096*2048];
__device__ __align__(16) unsigned char w8_Whh_mid[(size_t)4*4096*1024];
__device__ __align__(16) unsigned char w8_Wih_top[(size_t)4096*1024];
__device__ __align__(16) unsigned char w8_Whh_top[(size_t)4096*1024];
__device__ __align__(16) __half h_Wmid[(size_t)4*1024*1024];
__device__ __align__(16) __half h_Vmid[(size_t)4*1024*1024];
__device__ __align__(16) __half h_V1[(size_t)56*1024];
__device__ __align__(16) __half h_W0[(size_t)1024*56];

// ---------------- state / scratch ----------------------------------------------
__device__ float g_h[5][HH];
__device__ float g_c[2][5][HH];        // double-buffered (same-phase read/write)
__device__ float g_TD[4][HH];
__device__ float g_reconR[4][HH];
__device__ float g_recon1[CC];
__device__ float g_BU[HH];
__device__ float g_z[4*HH];
__device__ float g_loss_parts[TT][5];
__device__ volatile unsigned g_arrive[NBLK];   // flag-array grid barrier

// ---------------- helpers -----------------------------------------------------
__device__ __forceinline__ float ldf(const float* p) { return __ldcg(p); }
__device__ __forceinline__ void  stf(float* p, float v) { __stcg(p, v); }

__device__ __forceinline__ float warp_red(float v) {
#pragma unroll
    for (int o = 16; o; o >>= 1) v += __shfl_xor_sync(0xffffffffu, v, o);
    return v;
}

__device__ __forceinline__ __half2 cvt8(unsigned v16) {
    __half2_raw r = __nv_cvt_fp8x2_to_halfraw2((__nv_fp8x2_storage_t)v16, __NV_E4M3);
    return *reinterpret_cast<__half2*>(&r);
}
__device__ __forceinline__ float hsum(__half2 h) {
    float2 f = __half22float2(h);
    return f.x + f.y;
}

// fp8 weights (global, row base 16B-aligned) dot fp16 x (smem). nbytes in {1024,2048}.
__device__ __forceinline__ float dot_fp8(const unsigned char* __restrict__ w,
                                         const __half2* __restrict__ x,
                                         int nbytes, int lane) {
    float acc = 0.f;
#pragma unroll
    for (int c = lane * 16; c < nbytes; c += 512) {
        uint4 wv = *reinterpret_cast<const uint4*>(w + c);
        const uint4* xp = reinterpret_cast<const uint4*>(reinterpret_cast<const char*>(x) + 2 * c);
        uint4 xv0 = xp[0];
        uint4 xv1 = xp[1];
        const __half2* xa = reinterpret_cast<const __half2*>(&xv0);
        const __half2* xb = reinterpret_cast<const __half2*>(&xv1);
        __half2 s = __floats2half2_rn(0.f, 0.f);
        s = __hfma2(cvt8(wv.x & 0xffffu), xa[0], s);
        s = __hfma2(cvt8(wv.x >> 16),     xa[1], s);
        s = __hfma2(cvt8(wv.y & 0xffffu), xa[2], s);
        s = __hfma2(cvt8(wv.y >> 16),     xa[3], s);
        s = __hfma2(cvt8(wv.z & 0xffffu), xb[0], s);
        s = __hfma2(cvt8(wv.z >> 16),     xb[1], s);
        s = __hfma2(cvt8(wv.w & 0xffffu), xb[2], s);
        s = __hfma2(cvt8(wv.w >> 16),     xb[3], s);
        acc += hsum(s);
    }
    return acc;
}

// fp16 weights dot fp16 x (smem). nbytes = 2048 for 1024-elem rows.
__device__ __forceinline__ float dot_fp16(const __half* __restrict__ w,
                                          const __half* __restrict__ x,
                                          int nbytes, int lane) {
    float acc = 0.f;
#pragma unroll
    for (int c = lane * 16; c < nbytes; c += 512) {
        uint4 wv = *reinterpret_cast<const uint4*>(reinterpret_cast<const char*>(w) + c);
        uint4 xv = *reinterpret_cast<const uint4*>(reinterpret_cast<const char*>(x) + c);
        const __half2* wa = reinterpret_cast<const __half2*>(&wv);
        const __half2* xa = reinterpret_cast<const __half2*>(&xv);
        __half2 s = __floats2half2_rn(0.f, 0.f);
        s = __hfma2(wa[0], xa[0], s);
        s = __hfma2(wa[1], xa[1], s);
        s = __hfma2(wa[2], xa[2], s);
        s = __hfma2(wa[3], xa[3], s);
        acc += hsum(s);
    }
    return acc;
}

// 56-wide dot: fp16 weights, fp32 x (smem)
__device__ __forceinline__ float dot56h(const __half* __restrict__ w,
                                        const float* __restrict__ x, int lane) {
    float acc = 0.f;
    if (lane < 28) {
        __half2 h = *reinterpret_cast<const __half2*>(w + lane * 2);
        float2 f = __half22float2(h);
        acc = f.x * x[lane * 2] + f.y * x[lane * 2 + 1];
    }
    return acc;
}

__device__ __forceinline__ float sigm(float x) { return 1.f / (1.f + __expf(-x)); }

// flag-array grid barrier: each block stores epoch to own slot; warp 0 polls all.
__device__ __forceinline__ void gsync(unsigned ep) {
    __threadfence();
    __syncthreads();
    if (threadIdx.x < 32) {
        if (threadIdx.x == 0) g_arrive[blockIdx.x] = ep;
        int lane = threadIdx.x;
        for (;;) {
            unsigned v[5];
#pragma unroll
            for (int j = 0; j < 5; j++) {
                int s = lane + j * 32;
                v[j] = (s < NBLK) ? g_arrive[s] : 0xffffffffu;
            }
            bool ok = true;
#pragma unroll
            for (int j = 0; j < 5; j++) ok &= (v[j] >= ep);
            if (__all_sync(0xffffffffu, ok)) break;
        }
        __threadfence();
    }
    __syncthreads();
}

__device__ __forceinline__ float block_sum(float v, float* sred) {
    int lane = threadIdx.x & 31, w = threadIdx.x >> 5;
    v = warp_red(v);
    if (lane == 0) sred[w] = v;
    __syncthreads();
    float r = 0.f;
    if (w == 0) {
        r = (lane < NTHR / 32) ? sred[lane] : 0.f;
        r = warp_red(r);
    }
    __syncthreads();
    return r;   // valid in warp 0
}

// ---------------- conversion pre-pass ------------------------------------------
__global__ void convert_kernel(const float* __restrict__ W0, const float* __restrict__ Wmid,
                               const float* __restrict__ V1, const float* __restrict__ Vmid,
                               const float* __restrict__ Wihm, const float* __restrict__ Whhm,
                               const float* __restrict__ Wiht, const float* __restrict__ Whht) {
    long i0 = (long)blockIdx.x * blockDim.x + threadIdx.x;
    long st = (long)gridDim.x * blockDim.x;
#define CVT16(dst, src, n)                                                     \
    for (long i = i0; i < (long)(n) / 2; i += st)                              \
        ((__half2*)(dst))[i] = __float22half2_rn(((const float2*)(src))[i]);
#define CVT8(dst, src, n)                                                      \
    for (long i = i0; i < (long)(n) / 4; i += st) {                            \
        float4 v = ((const float4*)(src))[i];                                  \
        unsigned lo = (unsigned)__nv_cvt_float2_to_fp8x2(                      \
            make_float2(v.x * 64.f, v.y * 64.f), __NV_SATFINITE, __NV_E4M3);   \
        unsigned hi = (unsigned)__nv_cvt_float2_to_fp8x2(                      \
            make_float2(v.z * 64.f, v.w * 64.f), __NV_SATFINITE, __NV_E4M3);   \
        ((unsigned*)(dst))[i] = lo | (hi << 16);                               \
    }
    CVT8(w8_Wih_mid, Wihm, 4L * 4096 * 2048)
    CVT8(w8_Whh_mid, Whhm, 4L * 4096 * 1024)
    CVT8(w8_Wih_top, Wiht, 4096L * 1024)
    CVT8(w8_Whh_top, Whht, 4096L * 1024)
    CVT16(h_Wmid, Wmid, 4L * 1024 * 1024)
    CVT16(h_Vmid, Vmid, 4L * 1024 * 1024)
    CVT16(h_V1, V1, 56L * 1024)
    CVT16(h_W0, W0, 1024L * 56)
#undef CVT16
#undef CVT8
}

// ---------------- main persistent kernel ----------------------------------------
__global__ void __launch_bounds__(NTHR, 1)
predcells_kernel(const float* __restrict__ x_seq,
                 const float* __restrict__ W0_b,  const float* __restrict__ Wmid_b,
                 const float* __restrict__ V1_b,  const float* __restrict__ Vmid_b,
                 const float* __restrict__ bmid,  const float* __restrict__ btop,
                 float* __restrict__ out) {
    __shared__ __half2 sxh[1536];   // [BU(512) | TD(512) | h(512)] in half2 units
    __shared__ __half  sTDh[HH];
    __shared__ __half  shh[HH];
    __shared__ float   sxf[64];
    __shared__ float   sred[32];

    const int tid  = threadIdx.x;
    const int lane = tid & 31;
    const int wid  = tid >> 5;
    const int gw   = blockIdx.x * (NTHR / 32) + wid;
    const long gtid = (long)blockIdx.x * NTHR + tid;
    const long gsz  = (long)NBLK * NTHR;

    unsigned ep = g_arrive[blockIdx.x];   // all blocks hold identical value here

    // ---- prologue: zero carries, TD0/BU0 for t=0, loss0(t=0) ----
    for (long i = gtid; i < 5 * HH; i += gsz) { int l = (int)(i >> 10), k = (int)(i & 1023); g_h[l][k] = 0.f; g_c[0][l][k] = 0.f; }
    for (long i = gtid; i < 4 * HH; i += gsz) { int l = (int)(i >> 10), k = (int)(i & 1023); g_TD[l][k] = 0.f; g_reconR[l][k] = 0.f; }
    for (long i = gtid; i < CC; i += gsz) g_recon1[i] = 0.f;
    if (tid < CC) sxf[tid] = fabsf(x_seq[tid]);      // TD0(t=0) = |x_0|
    __syncthreads();
    if (gw < HH) {
        float a = warp_red(dot56h(&h_W0[(size_t)gw * CC], sxf, lane));
        if (lane == 0) stf(&g_BU[gw], a + W0_b[gw]);
    }
    if (blockIdx.x == 0) {
        float s = block_sum((tid < CC) ? sxf[tid] : 0.f, sred);
        if (tid == 0) stf(&g_loss_parts[0][0], s);
    }
    gsync(++ep);

    for (int t = 0; t < TT; t++) {
        const int p = t & 1;

#pragma unroll 1
        for (int m = 0; m < 4; m++) {
            // ---- LSTM phase m: z = Wih·[BU;TD[m]] + Whh·h[m] + b ----
            for (int i = tid; i < 1536; i += NTHR) {
                int e = i * 2;
                float a, b;
                if (e < HH)          { a = ldf(&g_BU[e]);            b = ldf(&g_BU[e + 1]); }
                else if (e < 2 * HH) { a = ldf(&g_TD[m][e - HH]);    b = ldf(&g_TD[m][e - HH + 1]); }
                else                 { a = ldf(&g_h[m][e - 2 * HH]); b = ldf(&g_h[m][e - 2 * HH + 1]); }
                sxh[i] = __floats2half2_rn(a, b);
            }
            __syncthreads();
            if (gw < 4096) {
                const unsigned char* wih = w8_Wih_mid + ((size_t)m * 4096 + gw) * 2048;
                const unsigned char* whh = w8_Whh_mid + ((size_t)m * 4096 + gw) * 1024;
                float a = dot_fp8(wih, sxh, 2048, lane)
                        + dot_fp8(whh, sxh + 1024, 1024, lane);
                a = warp_red(a);
                if (lane == 0) stf(&g_z[gw], a * INV_WSCALE + bmid[m * 4096 + gw]);
            }
            gsync(++ep);

            // ---- X phase m: gates, TD, BU = Wmid·TD, recon ----
            float td_val;
            {
                const int k = tid;
                float zi = ldf(&g_z[k]),        zf = ldf(&g_z[HH + k]);
                float zg = ldf(&g_z[2 * HH + k]), zo = ldf(&g_z[3 * HH + k]);
                float c_old = ldf(&g_c[p][m][k]);
                float cn = sigm(zf) * c_old + sigm(zi) * tanhf(zg);
                float hn = sigm(zo) * tanhf(cn);
                td_val = fabsf(hn - ldf(&g_reconR[m][k]));
                sTDh[k] = __float2half_rn(td_val);
                shh[k]  = __float2half_rn(hn);
                if (blockIdx.x == 0) {
                    stf(&g_c[1 - p][m][k], cn);
                    stf(&g_h[m][k], hn);
                    stf(&g_TD[m][k], td_val);
                }
            }
            __syncthreads();
            const int nrec = (m == 0) ? CC : HH;
            if (gw < HH) {
                float a = warp_red(dot_fp16(&h_Wmid[((size_t)m * HH + gw) * HH], sTDh, 2048, lane));
                if (lane == 0) stf(&g_BU[gw], a + Wmid_b[m * HH + gw]);
            } else if (gw < HH + nrec) {
                int r = gw - HH;
                if (m == 0) {
                    float a = warp_red(dot_fp16(&h_V1[(size_t)r * HH], shh, 2048, lane));
                    if (lane == 0) stf(&g_recon1[r], a + V1_b[r]);
                } else {
                    float a = warp_red(dot_fp16(&h_Vmid[((size_t)(m - 1) * HH + r) * HH], shh, 2048, lane));
                    if (lane == 0) stf(&g_reconR[m - 1][r], a + Vmid_b[(m - 1) * HH + r]);
                }
            }
            if (blockIdx.x == 0) {
                float s = block_sum(td_val, sred);
                if (tid == 0) stf(&g_loss_parts[t][1 + m], s);
            }
            gsync(++ep);
        }

        // ---- top LSTM phase: z = Wih_top·BU + Whh_top·h[4] + b ----
        for (int i = tid; i < 1024; i += NTHR) {
            int e = i * 2;
            float a, b;
            if (e < HH) { a = ldf(&g_BU[e]);          b = ldf(&g_BU[e + 1]); }
            else        { a = ldf(&g_h[4][e - HH]);   b = ldf(&g_h[4][e - HH + 1]); }
            sxh[i] = __floats2half2_rn(a, b);
        }
        __syncthreads();
        if (gw < 4096) {
            float a = dot_fp8(w8_Wih_top + (size_t)gw * 1024, sxh, 1024, lane)
                    + dot_fp8(w8_Whh_top + (size_t)gw * 1024, sxh + 512, 1024, lane);
            a = warp_red(a);
            if (lane == 0) stf(&g_z[gw], a * INV_WSCALE + btop[gw]);
        }
        gsync(++ep);

        // ---- X5: top gates, recon_top = Vmid[3]·h5; fused TD0/BU0/loss0 for t+1 ----
        {
            const bool more = (t + 1 < TT);
            {
                const int k = tid;
                float zi = ldf(&g_z[k]),          zf = ldf(&g_z[HH + k]);
                float zg = ldf(&g_z[2 * HH + k]), zo = ldf(&g_z[3 * HH + k]);
                float c_old = ldf(&g_c[p][4][k]);
                float cn = sigm(zf) * c_old + sigm(zi) * tanhf(zg);
                float hn = sigm(zo) * tanhf(cn);
                shh[k] = __float2half_rn(hn);
                if (blockIdx.x == 0) {
                    stf(&g_c[1 - p][4][k], cn);
                    stf(&g_h[4][k], hn);
                }
            }
            if (more && tid < CC)
                sxf[tid] = fabsf(x_seq[(t + 1) * CC + tid] - ldf(&g_recon1[tid]));
            __syncthreads();
            if (gw < HH) {
                float a = warp_red(dot_fp16(&h_Vmid[((size_t)3 * HH + gw) * HH], shh, 2048, lane));
                if (lane == 0) stf(&g_reconR[3][gw], a + Vmid_b[3 * HH + gw]);
            } else if (more && gw < 2 * HH) {
                int r = gw - HH;
                float a = warp_red(dot56h(&h_W0[(size_t)r * CC], sxf, lane));
                if (lane == 0) stf(&g_BU[r], a + W0_b[r]);
            }
            if (more && blockIdx.x == 0) {
                float s = block_sum((tid < CC) ? sxf[tid] : 0.f, sred);
                if (tid == 0) stf(&g_loss_parts[t + 1][0], s);
            }
            gsync(++ep);
        }
    }

    // ---- epilogue: deterministic loss reduction (all parts written by block 0) ----
    if (blockIdx.x == 0) {
        const float* parts = &g_loss_parts[0][0];
        float v = 0.f;
        for (int i = tid; i < TT * 5; i += NTHR) v += ldf(&parts[i]);
        float s = block_sum(v, sred);
        if (tid == 0) out[0] = s;
    }
}

// ---------------- launch ---------------------------------------------------------
extern "C" void kernel_launch(void* const* d_in, const int* in_sizes, int n_in,
                              void* d_out, int out_size) {
    (void)in_sizes; (void)n_in; (void)out_size;
    const float* x_seq  = (const float*)d_in[0];
    const float* W0_w   = (const float*)d_in[1];
    const float* W0_b   = (const float*)d_in[2];
    const float* Wmid_w = (const float*)d_in[3];
    const float* Wmid_b = (const float*)d_in[4];
    const float* V1_w   = (const float*)d_in[5];
    const float* V1_b   = (const float*)d_in[6];
    const float* Vmid_w = (const float*)d_in[7];
    const float* Vmid_b = (const float*)d_in[8];
    const float* Wihm   = (const float*)d_in[9];
    const float* Whhm   = (const float*)d_in[10];
    const float* bmid   = (const float*)d_in[11];
    const float* Wiht   = (const float*)d_in[12];
    const float* Whht   = (const float*)d_in[13];
    const float* btop   = (const float*)d_in[14];

    convert_kernel<<<2048, 256>>>(W0_w, Wmid_w, V1_w, Vmid_w, Wihm, Whhm, Wiht, Whht);
    predcells_kernel<<<NBLK, NTHR>>>(x_seq, W0_b, Wmid_b, V1_b, Vmid_b, bmid, btop,
                                     (float*)d_out);
}

// round 3
// speedup vs baseline: 1.6888x; 1.5092x over previous
#include <cuda_runtime.h>
#include <cuda_fp16.h>
#include <cuda_fp8.h>

#define TT 256
#define CC 56
#define HH 1024
#define NBLK 148
#define NTHR 1024
#define INV_WSCALE (1.0f/64.0f)

// ---------------- quantized weights (filled by convert_kernel each launch) ----
__device__ __align__(16) unsigned char w8_Wih_mid[(size_t)4*4096*2048];
__device__ __align__(16) unsigned char w8_Whh_mid[(size_t)4*4096*1024];
__device__ __align__(16) unsigned char w8_Wih_top[(size_t)4096*1024];
__device__ __align__(16) unsigned char w8_Whh_top[(size_t)4096*1024];
__device__ __align__(16) __half h_Wmid[(size_t)4*1024*1024];
__device__ __align__(16) __half h_Vmid[(size_t)4*1024*1024];
__device__ __align__(16) __half h_V1[(size_t)56*1024];
__device__ __align__(16) __half h_W0[(size_t)1024*56];

// ---------------- state / scratch ----------------------------------------------
// g_xin[m] = [BU(1024) | TD_prev(1024) | h_prev(1024)] halves, contiguous per layer
__device__ __align__(16) __half g_xin[4][3*HH];
__device__ __align__(16) __half g_xtop[2*HH];      // [BU5 | h5_prev]
__device__ float g_c[2][5][HH];
__device__ float g_reconR[4][HH];
__device__ float g_recon1[CC];
__device__ float g_z[4*HH];
__device__ float g_loss_parts[TT][5];
__device__ unsigned g_arrive[NBLK];

// ---------------- helpers -----------------------------------------------------
__device__ __forceinline__ float ldf(const float* p) { return __ldcg(p); }
__device__ __forceinline__ void  stf(float* p, float v) { __stcg(p, v); }

__device__ __forceinline__ float warp_red(float v) {
#pragma unroll
    for (int o = 16; o; o >>= 1) v += __shfl_xor_sync(0xffffffffu, v, o);
    return v;
}

__device__ __forceinline__ __half2 cvt8(unsigned v16) {
    __half2_raw r = __nv_cvt_fp8x2_to_halfraw2((__nv_fp8x2_storage_t)v16, __NV_E4M3);
    return *reinterpret_cast<__half2*>(&r);
}
__device__ __forceinline__ float hsum(__half2 h) {
    float2 f = __half22float2(h);
    return f.x + f.y;
}

// fp8 weights dot fp16 x (smem). NB = row bytes (1024 or 2048), fully unrolled.
template<int NB>
__device__ __forceinline__ float dot8(const unsigned char* __restrict__ w,
                                      const __half* __restrict__ x, int lane) {
    float acc = 0.f;
#pragma unroll
    for (int it = 0; it < NB / 512; it++) {
        int c = it * 512 + lane * 16;
        uint4 wv  = *reinterpret_cast<const uint4*>(w + c);
        uint4 xv0 = *reinterpret_cast<const uint4*>(reinterpret_cast<const char*>(x) + 2 * c);
        uint4 xv1 = *reinterpret_cast<const uint4*>(reinterpret_cast<const char*>(x) + 2 * c + 16);
        const __half2* xa = reinterpret_cast<const __half2*>(&xv0);
        const __half2* xb = reinterpret_cast<const __half2*>(&xv1);
        __half2 s = __floats2half2_rn(0.f, 0.f);
        s = __hfma2(cvt8(wv.x & 0xffffu), xa[0], s);
        s = __hfma2(cvt8(wv.x >> 16),     xa[1], s);
        s = __hfma2(cvt8(wv.y & 0xffffu), xa[2], s);
        s = __hfma2(cvt8(wv.y >> 16),     xa[3], s);
        s = __hfma2(cvt8(wv.z & 0xffffu), xb[0], s);
        s = __hfma2(cvt8(wv.z >> 16),     xb[1], s);
        s = __hfma2(cvt8(wv.w & 0xffffu), xb[2], s);
        s = __hfma2(cvt8(wv.w >> 16),     xb[3], s);
        acc += hsum(s);
    }
    return acc;
}

// fp16 weights dot fp16 x (smem). NB = row bytes (2048), fully unrolled.
template<int NB>
__device__ __forceinline__ float dot16(const __half* __restrict__ w,
                                       const __half* __restrict__ x, int lane) {
    float acc = 0.f;
#pragma unroll
    for (int it = 0; it < NB / 512; it++) {
        int c = it * 512 + lane * 16;
        uint4 wv = *reinterpret_cast<const uint4*>(reinterpret_cast<const char*>(w) + c);
        uint4 xv = *reinterpret_cast<const uint4*>(reinterpret_cast<const char*>(x) + c);
        const __half2* wa = reinterpret_cast<const __half2*>(&wv);
        const __half2* xa = reinterpret_cast<const __half2*>(&xv);
        __half2 s = __floats2half2_rn(0.f, 0.f);
        s = __hfma2(wa[0], xa[0], s);
        s = __hfma2(wa[1], xa[1], s);
        s = __hfma2(wa[2], xa[2], s);
        s = __hfma2(wa[3], xa[3], s);
        acc += hsum(s);
    }
    return acc;
}

// 56-wide dot: fp16 weights, fp32 x (smem)
__device__ __forceinline__ float dot56h(const __half* __restrict__ w,
                                        const float* __restrict__ x, int lane) {
    float acc = 0.f;
    if (lane < 28) {
        __half2 h = *reinterpret_cast<const __half2*>(w + lane * 2);
        float2 f = __half22float2(h);
        acc = f.x * x[lane * 2] + f.y * x[lane * 2 + 1];
    }
    return acc;
}

__device__ __forceinline__ float sigm(float x) { return 1.f / (1.f + __expf(-x)); }

// GPU-scope release/acquire grid barrier (no sys-scope volatiles, no threadfence).
__device__ __forceinline__ void gsync(unsigned ep) {
    __syncthreads();
    if (threadIdx.x < 32) {
        if (threadIdx.x == 0)
            asm volatile("st.release.gpu.global.b32 [%0], %1;"
                         :: "l"(g_arrive + blockIdx.x), "r"(ep) : "memory");
        const int lane = threadIdx.x;
        bool done = false;
        while (!done) {
            bool ok = true;
#pragma unroll
            for (int j = 0; j < 5; j++) {
                int s = lane + j * 32;
                if (s < NBLK) {
                    unsigned v;
                    asm volatile("ld.acquire.gpu.global.b32 %0, [%1];"
                                 : "=r"(v) : "l"(g_arrive + s) : "memory");
                    ok &= ((int)(v - ep) >= 0);
                }
            }
            done = __all_sync(0xffffffffu, ok);
        }
    }
    __syncthreads();
}

__device__ __forceinline__ float block_sum(float v, float* sred) {
    int lane = threadIdx.x & 31, w = threadIdx.x >> 5;
    v = warp_red(v);
    if (lane == 0) sred[w] = v;
    __syncthreads();
    float r = 0.f;
    if (w == 0) {
        r = (lane < NTHR / 32) ? sred[lane] : 0.f;
        r = warp_red(r);
    }
    __syncthreads();
    return r;   // valid in warp 0
}

// ---------------- conversion pre-pass ------------------------------------------
__global__ void convert_kernel(const float* __restrict__ W0, const float* __restrict__ Wmid,
                               const float* __restrict__ V1, const float* __restrict__ Vmid,
                               const float* __restrict__ Wihm, const float* __restrict__ Whhm,
                               const float* __restrict__ Wiht, const float* __restrict__ Whht) {
    long i0 = (long)blockIdx.x * blockDim.x + threadIdx.x;
    long st = (long)gridDim.x * blockDim.x;
#define CVT16(dst, src, n)                                                     \
    for (long i = i0; i < (long)(n) / 2; i += st)                              \
        ((__half2*)(dst))[i] = __float22half2_rn(((const float2*)(src))[i]);
#define CVT8(dst, src, n)                                                      \
    for (long i = i0; i < (long)(n) / 4; i += st) {                            \
        float4 v = ((const float4*)(src))[i];                                  \
        unsigned lo = (unsigned)__nv_cvt_float2_to_fp8x2(                      \
            make_float2(v.x * 64.f, v.y * 64.f), __NV_SATFINITE, __NV_E4M3);   \
        unsigned hi = (unsigned)__nv_cvt_float2_to_fp8x2(                      \
            make_float2(v.z * 64.f, v.w * 64.f), __NV_SATFINITE, __NV_E4M3);   \
        ((unsigned*)(dst))[i] = lo | (hi << 16);                               \
    }
    CVT8(w8_Wih_mid, Wihm, 4L * 4096 * 2048)
    CVT8(w8_Whh_mid, Whhm, 4L * 4096 * 1024)
    CVT8(w8_Wih_top, Wiht, 4096L * 1024)
    CVT8(w8_Whh_top, Whht, 4096L * 1024)
    CVT16(h_Wmid, Wmid, 4L * 1024 * 1024)
    CVT16(h_Vmid, Vmid, 4L * 1024 * 1024)
    CVT16(h_V1, V1, 56L * 1024)
    CVT16(h_W0, W0, 1024L * 56)
#undef CVT16
#undef CVT8
}

// ---------------- main persistent kernel ----------------------------------------
__global__ void __launch_bounds__(NTHR, 1)
predcells_kernel(const float* __restrict__ x_seq,
                 const float* __restrict__ W0_b,  const float* __restrict__ Wmid_b,
                 const float* __restrict__ V1_b,  const float* __restrict__ Vmid_b,
                 const float* __restrict__ bmid,  const float* __restrict__ btop,
                 float* __restrict__ out) {
    __shared__ __align__(16) __half sxh[3 * HH];
    __shared__ __align__(16) __half sTDh[HH];
    __shared__ __align__(16) __half shh[HH];
    __shared__ float sxf[64];
    __shared__ float sred[32];

    const int tid  = threadIdx.x;
    const int lane = tid & 31;
    const int wid  = tid >> 5;
    const int gw   = blockIdx.x * (NTHR / 32) + wid;
    const long gtid = (long)blockIdx.x * NTHR + tid;
    const long gsz  = (long)NBLK * NTHR;

    unsigned ep = g_arrive[blockIdx.x];   // all slots equal at entry

    // ---- prologue: zero carries, TD0/BU1 for t=0, loss0(t=0) ----
    const __half hz = __float2half_rn(0.f);
    for (long i = gtid; i < 5 * HH; i += gsz) { int l = (int)(i >> 10), k = (int)(i & 1023); g_c[0][l][k] = 0.f; }
    for (long i = gtid; i < 4 * HH; i += gsz) {
        int l = (int)(i >> 10), k = (int)(i & 1023);
        g_xin[l][HH + k] = hz; g_xin[l][2 * HH + k] = hz;   // TD_prev, h_prev = 0
        g_reconR[l][k] = 0.f;
    }
    for (long i = gtid; i < HH; i += gsz) g_xtop[HH + i] = hz;
    for (long i = gtid; i < CC; i += gsz) g_recon1[i] = 0.f;
    if (tid < CC) sxf[tid] = fabsf(x_seq[tid]);      // TD0(t=0) = |x_0|
    __syncthreads();
    if (gw < HH) {
        float a = warp_red(dot56h(&h_W0[(size_t)gw * CC], sxf, lane));
        if (lane == 0) g_xin[0][gw] = __float2half_rn(a + W0_b[gw]);
    }
    if (blockIdx.x == 0) {
        float s = block_sum((tid < CC) ? sxf[tid] : 0.f, sred);
        if (tid == 0) stf(&g_loss_parts[0][0], s);
    }
    gsync(++ep);

    for (int t = 0; t < TT; t++) {
        const int p = t & 1;

#pragma unroll 1
        for (int m = 0; m < 4; m++) {
            // ---- LSTM phase m: z = Wih·[BU;TD_prev] + Whh·h_prev + b ----
            if (tid < 384)
                reinterpret_cast<uint4*>(sxh)[tid] =
                    __ldcg(reinterpret_cast<const uint4*>(g_xin[m]) + tid);
            __syncthreads();
            if (gw < 4096) {
                const unsigned char* wih = w8_Wih_mid + ((size_t)m * 4096 + gw) * 2048;
                const unsigned char* whh = w8_Whh_mid + ((size_t)m * 4096 + gw) * 1024;
                float a = dot8<2048>(wih, sxh, lane)
                        + dot8<1024>(whh, sxh + 2 * HH, lane);
                a = warp_red(a);
                if (lane == 0) stf(&g_z[gw], a * INV_WSCALE + bmid[m * 4096 + gw]);
            }
            gsync(++ep);

            // ---- X phase m: gates, TD, BU = Wmid·TD, recon ----
            float td_val;
            {
                const int k = tid;
                float zi = ldf(&g_z[k]),          zf = ldf(&g_z[HH + k]);
                float zg = ldf(&g_z[2 * HH + k]), zo = ldf(&g_z[3 * HH + k]);
                float c_old = ldf(&g_c[p][m][k]);
                float cn = sigm(zf) * c_old + sigm(zi) * tanhf(zg);
                float hn = sigm(zo) * tanhf(cn);
                td_val = fabsf(hn - ldf(&g_reconR[m][k]));
                __half tdh = __float2half_rn(td_val);
                __half hnh = __float2half_rn(hn);
                sTDh[k] = tdh;
                shh[k]  = hnh;
                if (blockIdx.x == 0) {
                    stf(&g_c[1 - p][m][k], cn);
                    g_xin[m][HH + k]     = tdh;   // TD carry for next step
                    g_xin[m][2 * HH + k] = hnh;   // h carry for next step
                }
            }
            __syncthreads();
            const int nrec = (m == 0) ? CC : HH;
            if (gw < HH) {
                float a = warp_red(dot16<2048>(&h_Wmid[((size_t)m * HH + gw) * HH], sTDh, lane));
                __half r = __float2half_rn(a + Wmid_b[m * HH + gw]);
                if (lane == 0) { if (m < 3) g_xin[m + 1][gw] = r; else g_xtop[gw] = r; }
            } else if (gw < HH + nrec) {
                int r = gw - HH;
                if (m == 0) {
                    float a = warp_red(dot16<2048>(&h_V1[(size_t)r * HH], shh, lane));
                    if (lane == 0) stf(&g_recon1[r], a + V1_b[r]);
                } else {
                    float a = warp_red(dot16<2048>(&h_Vmid[((size_t)(m - 1) * HH + r) * HH], shh, lane));
                    if (lane == 0) stf(&g_reconR[m - 1][r], a + Vmid_b[(m - 1) * HH + r]);
                }
            }
            if (blockIdx.x == 0) {
                float s = block_sum(td_val, sred);
                if (tid == 0) stf(&g_loss_parts[t][1 + m], s);
            }
            gsync(++ep);
        }

        // ---- top LSTM phase: z = Wih_top·BU5 + Whh_top·h5_prev + b ----
        if (tid < 256)
            reinterpret_cast<uint4*>(sxh)[tid] =
                __ldcg(reinterpret_cast<const uint4*>(g_xtop) + tid);
        __syncthreads();
        if (gw < 4096) {
            float a = dot8<1024>(w8_Wih_top + (size_t)gw * 1024, sxh, lane)
                    + dot8<1024>(w8_Whh_top + (size_t)gw * 1024, sxh + HH, lane);
            a = warp_red(a);
            if (lane == 0) stf(&g_z[gw], a * INV_WSCALE + btop[gw]);
        }
        gsync(++ep);

        // ---- X5: top gates, recon_top = Vmid[3]·h5; fused TD0/BU1/loss0 for t+1 ----
        {
            const bool more = (t + 1 < TT);
            {
                const int k = tid;
                float zi = ldf(&g_z[k]),          zf = ldf(&g_z[HH + k]);
                float zg = ldf(&g_z[2 * HH + k]), zo = ldf(&g_z[3 * HH + k]);
                float c_old = ldf(&g_c[p][4][k]);
                float cn = sigm(zf) * c_old + sigm(zi) * tanhf(zg);
                float hn = sigm(zo) * tanhf(cn);
                __half hnh = __float2half_rn(hn);
                shh[k] = hnh;
                if (blockIdx.x == 0) {
                    stf(&g_c[1 - p][4][k], cn);
                    g_xtop[HH + k] = hnh;
                }
            }
            if (more && tid < CC)
                sxf[tid] = fabsf(x_seq[(t + 1) * CC + tid] - ldf(&g_recon1[tid]));
            __syncthreads();
            if (gw < HH) {
                float a = warp_red(dot16<2048>(&h_Vmid[((size_t)3 * HH + gw) * HH], shh, lane));
                if (lane == 0) stf(&g_reconR[3][gw], a + Vmid_b[3 * HH + gw]);
            } else if (more && gw < 2 * HH) {
                int r = gw - HH;
                float a = warp_red(dot56h(&h_W0[(size_t)r * CC], sxf, lane));
                if (lane == 0) g_xin[0][r] = __float2half_rn(a + W0_b[r]);
            }
            if (more && blockIdx.x == 0) {
                float s = block_sum((tid < CC) ? sxf[tid] : 0.f, sred);
                if (tid == 0) stf(&g_loss_parts[t + 1][0], s);
            }
            gsync(++ep);
        }
    }

    // ---- epilogue: deterministic loss reduction (all parts written by block 0) ----
    if (blockIdx.x == 0) {
        const float* parts = &g_loss_parts[0][0];
        float v = 0.f;
        for (int i = tid; i < TT * 5; i += NTHR) v += ldf(&parts[i]);
        float s = block_sum(v, sred);
        if (tid == 0) out[0] = s;
    }
}

// ---------------- launch ---------------------------------------------------------
extern "C" void kernel_launch(void* const* d_in, const int* in_sizes, int n_in,
                              void* d_out, int out_size) {
    (void)in_sizes; (void)n_in; (void)out_size;
    const float* x_seq  = (const float*)d_in[0];
    const float* W0_w   = (const float*)d_in[1];
    const float* W0_b   = (const float*)d_in[2];
    const float* Wmid_w = (const float*)d_in[3];
    const float* Wmid_b = (const float*)d_in[4];
    const float* V1_w   = (const float*)d_in[5];
    const float* V1_b   = (const float*)d_in[6];
    const float* Vmid_w = (const float*)d_in[7];
    const float* Vmid_b = (const float*)d_in[8];
    const float* Wihm   = (const float*)d_in[9];
    const float* Whhm   = (const float*)d_in[10];
    const float* bmid   = (const float*)d_in[11];
    const float* Wiht   = (const float*)d_in[12];
    const float* Whht   = (const float*)d_in[13];
    const float* btop   = (const float*)d_in[14];

    convert_kernel<<<2048, 256>>>(W0_w, Wmid_w, V1_w, Vmid_w, Wihm, Whhm, Wiht, Whht);
    predcells_kernel<<<NBLK, NTHR>>>(x_seq, W0_b, Wmid_b, V1_b, Vmid_b, bmid, btop,
                                     (float*)d_out);
}

// round 4
// speedup vs baseline: 1.9351x; 1.1459x over previous
#include <cuda_runtime.h>
#include <cuda_fp16.h>
#include <cuda_fp8.h>

#define TT 256
#define CC 56
#define HH 1024
#define NBLK 148
#define NTHR 1024
#define INV_WSCALE (1.0f/64.0f)

// ---------------- quantized weights (filled by convert_kernel each launch) ----
__device__ __align__(16) unsigned char w8_Wih_mid[(size_t)4*4096*2048];
__device__ __align__(16) unsigned char w8_Whh_mid[(size_t)4*4096*1024];
__device__ __align__(16) unsigned char w8_Wih_top[(size_t)4096*1024];
__device__ __align__(16) unsigned char w8_Whh_top[(size_t)4096*1024];
__device__ __align__(16) __half h_Wmid[(size_t)4*1024*1024];
__device__ __align__(16) __half h_Vmid[(size_t)4*1024*1024];
__device__ __align__(16) __half h_V1[(size_t)56*1024];
__device__ __align__(16) __half h_W0[(size_t)1024*56];

// ---------------- state / scratch ----------------------------------------------
// g_xin[m] = [BU(1024) | TD_prev(1024) | h_prev(1024)] halves, contiguous per layer
__device__ __align__(16) __half g_xin[4][3*HH];
__device__ __align__(16) __half g_xtop[2*HH];      // [BU5 | h5_prev]
__device__ float g_c[2][5][HH];
__device__ float g_reconR[4][HH];
__device__ float g_recon1[CC];
__device__ float g_z[4*HH];
__device__ float g_loss_parts[TT][5];
__device__ unsigned g_arrive[NBLK];

// ---------------- helpers -----------------------------------------------------
__device__ __forceinline__ float ldf(const float* p) { return __ldcg(p); }
__device__ __forceinline__ void  stf(float* p, float v) { __stcg(p, v); }

__device__ __forceinline__ float warp_red(float v) {
#pragma unroll
    for (int o = 16; o; o >>= 1) v += __shfl_xor_sync(0xffffffffu, v, o);
    return v;
}

__device__ __forceinline__ __half2 cvt8(unsigned v16) {
    __half2_raw r = __nv_cvt_fp8x2_to_halfraw2((__nv_fp8x2_storage_t)v16, __NV_E4M3);
    return *reinterpret_cast<__half2*>(&r);
}
__device__ __forceinline__ float hsum(__half2 h) {
    float2 f = __half22float2(h);
    return f.x + f.y;
}

// fp8 weights dot fp16 x (smem). NB = row bytes (1024 or 2048), fully unrolled.
template<int NB>
__device__ __forceinline__ float dot8(const unsigned char* __restrict__ w,
                                      const __half* __restrict__ x, int lane) {
    float acc = 0.f;
#pragma unroll
    for (int it = 0; it < NB / 512; it++) {
        int c = it * 512 + lane * 16;
        uint4 wv  = *reinterpret_cast<const uint4*>(w + c);
        uint4 xv0 = *reinterpret_cast<const uint4*>(reinterpret_cast<const char*>(x) + 2 * c);
        uint4 xv1 = *reinterpret_cast<const uint4*>(reinterpret_cast<const char*>(x) + 2 * c + 16);
        const __half2* xa = reinterpret_cast<const __half2*>(&xv0);
        const __half2* xb = reinterpret_cast<const __half2*>(&xv1);
        __half2 s = __floats2half2_rn(0.f, 0.f);
        s = __hfma2(cvt8(wv.x & 0xffffu), xa[0], s);
        s = __hfma2(cvt8(wv.x >> 16),     xa[1], s);
        s = __hfma2(cvt8(wv.y & 0xffffu), xa[2], s);
        s = __hfma2(cvt8(wv.y >> 16),     xa[3], s);
        s = __hfma2(cvt8(wv.z & 0xffffu), xb[0], s);
        s = __hfma2(cvt8(wv.z >> 16),     xb[1], s);
        s = __hfma2(cvt8(wv.w & 0xffffu), xb[2], s);
        s = __hfma2(cvt8(wv.w >> 16),     xb[3], s);
        acc += hsum(s);
    }
    return acc;
}

// fp16 weights dot fp16 x (smem). NB = row bytes (2048), fully unrolled.
template<int NB>
__device__ __forceinline__ float dot16(const __half* __restrict__ w,
                                       const __half* __restrict__ x, int lane) {
    float acc = 0.f;
#pragma unroll
    for (int it = 0; it < NB / 512; it++) {
        int c = it * 512 + lane * 16;
        uint4 wv = *reinterpret_cast<const uint4*>(reinterpret_cast<const char*>(w) + c);
        uint4 xv = *reinterpret_cast<const uint4*>(reinterpret_cast<const char*>(x) + c);
        const __half2* wa = reinterpret_cast<const __half2*>(&wv);
        const __half2* xa = reinterpret_cast<const __half2*>(&xv);
        __half2 s = __floats2half2_rn(0.f, 0.f);
        s = __hfma2(wa[0], xa[0], s);
        s = __hfma2(wa[1], xa[1], s);
        s = __hfma2(wa[2], xa[2], s);
        s = __hfma2(wa[3], xa[3], s);
        acc += hsum(s);
    }
    return acc;
}

// 56-wide dot: fp16 weights, fp32 x (smem)
__device__ __forceinline__ float dot56h(const __half* __restrict__ w,
                                        const float* __restrict__ x, int lane) {
    float acc = 0.f;
    if (lane < 28) {
        __half2 h = *reinterpret_cast<const __half2*>(w + lane * 2);
        float2 f = __half22float2(h);
        acc = f.x * x[lane * 2] + f.y * x[lane * 2 + 1];
    }
    return acc;
}

__device__ __forceinline__ float sigm(float x) { return 1.f / (1.f + __expf(-x)); }

// GPU-scope release/acquire grid barrier (no sys-scope volatiles, no threadfence).
__device__ __forceinline__ void gsync(unsigned ep) {
    __syncthreads();
    if (threadIdx.x < 32) {
        if (threadIdx.x == 0)
            asm volatile("st.release.gpu.global.b32 [%0], %1;"
                         :: "l"(g_arrive + blockIdx.x), "r"(ep) : "memory");
        const int lane = threadIdx.x;
        bool done = false;
        while (!done) {
            bool ok = true;
#pragma unroll
            for (int j = 0; j < 5; j++) {
                int s = lane + j * 32;
                if (s < NBLK) {
                    unsigned v;
                    asm volatile("ld.acquire.gpu.global.b32 %0, [%1];"
                                 : "=r"(v) : "l"(g_arrive + s) : "memory");
                    ok &= ((int)(v - ep) >= 0);
                }
            }
            done = __all_sync(0xffffffffu, ok);
        }
    }
    __syncthreads();
}

__device__ __forceinline__ float block_sum(float v, float* sred) {
    int lane = threadIdx.x & 31, w = threadIdx.x >> 5;
    v = warp_red(v);
    if (lane == 0) sred[w] = v;
    __syncthreads();
    float r = 0.f;
    if (w == 0) {
        r = (lane < NTHR / 32) ? sred[lane] : 0.f;
        r = warp_red(r);
    }
    __syncthreads();
    return r;   // valid in warp 0
}

// ---------------- conversion pre-pass ------------------------------------------
__global__ void convert_kernel(const float* __restrict__ W0, const float* __restrict__ Wmid,
                               const float* __restrict__ V1, const float* __restrict__ Vmid,
                               const float* __restrict__ Wihm, const float* __restrict__ Whhm,
                               const float* __restrict__ Wiht, const float* __restrict__ Whht) {
    long i0 = (long)blockIdx.x * blockDim.x + threadIdx.x;
    long st = (long)gridDim.x * blockDim.x;
#define CVT16(dst, src, n)                                                     \
    for (long i = i0; i < (long)(n) / 2; i += st)                              \
        ((__half2*)(dst))[i] = __float22half2_rn(((const float2*)(src))[i]);
#define CVT8(dst, src, n)                                                      \
    for (long i = i0; i < (long)(n) / 4; i += st) {                            \
        float4 v = ((const float4*)(src))[i];                                  \
        unsigned lo = (unsigned)__nv_cvt_float2_to_fp8x2(                      \
            make_float2(v.x * 64.f, v.y * 64.f), __NV_SATFINITE, __NV_E4M3);   \
        unsigned hi = (unsigned)__nv_cvt_float2_to_fp8x2(                      \
            make_float2(v.z * 64.f, v.w * 64.f), __NV_SATFINITE, __NV_E4M3);   \
        ((unsigned*)(dst))[i] = lo | (hi << 16);                               \
    }
    CVT8(w8_Wih_mid, Wihm, 4L * 4096 * 2048)
    CVT8(w8_Whh_mid, Whhm, 4L * 4096 * 1024)
    CVT8(w8_Wih_top, Wiht, 4096L * 1024)
    CVT8(w8_Whh_top, Whht, 4096L * 1024)
    CVT16(h_Wmid, Wmid, 4L * 1024 * 1024)
    CVT16(h_Vmid, Vmid, 4L * 1024 * 1024)
    CVT16(h_V1, V1, 56L * 1024)
    CVT16(h_W0, W0, 1024L * 56)
#undef CVT16
#undef CVT8
}

// ---------------- main persistent kernel ----------------------------------------
__global__ void __launch_bounds__(NTHR, 1)
predcells_kernel(const float* __restrict__ x_seq,
                 const float* __restrict__ W0_b,  const float* __restrict__ Wmid_b,
                 const float* __restrict__ V1_b,  const float* __restrict__ Vmid_b,
                 const float* __restrict__ bmid,  const float* __restrict__ btop,
                 float* __restrict__ out) {
    __shared__ __align__(16) __half sxh[3 * HH];
    __shared__ __align__(16) __half sTDh[HH];
    __shared__ __align__(16) __half shh[HH];
    __shared__ float sxf[64];
    __shared__ float sred[32];

    const int tid  = threadIdx.x;
    const int lane = tid & 31;
    const int wid  = tid >> 5;
    const int gw   = blockIdx.x * (NTHR / 32) + wid;
    const long gtid = (long)blockIdx.x * NTHR + tid;
    const long gsz  = (long)NBLK * NTHR;

    unsigned ep = g_arrive[blockIdx.x];   // all slots equal at entry

    // ---- prologue: zero carries, TD0/BU1 for t=0, loss0(t=0) ----
    const __half hz = __float2half_rn(0.f);
    for (long i = gtid; i < 5 * HH; i += gsz) { int l = (int)(i >> 10), k = (int)(i & 1023); g_c[0][l][k] = 0.f; }
    for (long i = gtid; i < 4 * HH; i += gsz) {
        int l = (int)(i >> 10), k = (int)(i & 1023);
        g_xin[l][HH + k] = hz; g_xin[l][2 * HH + k] = hz;   // TD_prev, h_prev = 0
        g_reconR[l][k] = 0.f;
    }
    for (long i = gtid; i < HH; i += gsz) g_xtop[HH + i] = hz;
    for (long i = gtid; i < CC; i += gsz) g_recon1[i] = 0.f;
    if (tid < CC) sxf[tid] = fabsf(x_seq[tid]);      // TD0(t=0) = |x_0|
    __syncthreads();
    if (gw < HH) {
        float a = warp_red(dot56h(&h_W0[(size_t)gw * CC], sxf, lane));
        if (lane == 0) g_xin[0][gw] = __float2half_rn(a + W0_b[gw]);
    }
    if (blockIdx.x == 0) {
        float s = block_sum((tid < CC) ? sxf[tid] : 0.f, sred);
        if (tid == 0) stf(&g_loss_parts[0][0], s);
    }
    gsync(++ep);

    for (int t = 0; t < TT; t++) {
        const int p = t & 1;

#pragma unroll 1
        for (int m = 0; m < 4; m++) {
            // ---- LSTM phase m: z = Wih·[BU;TD_prev] + Whh·h_prev + b ----
            if (tid < 384)
                reinterpret_cast<uint4*>(sxh)[tid] =
                    __ldcg(reinterpret_cast<const uint4*>(g_xin[m]) + tid);
            __syncthreads();
            if (gw < 4096) {
                const unsigned char* wih = w8_Wih_mid + ((size_t)m * 4096 + gw) * 2048;
                const unsigned char* whh = w8_Whh_mid + ((size_t)m * 4096 + gw) * 1024;
                float a = dot8<2048>(wih, sxh, lane)
                        + dot8<1024>(whh, sxh + 2 * HH, lane);
                a = warp_red(a);
                if (lane == 0) stf(&g_z[gw], a * INV_WSCALE + bmid[m * 4096 + gw]);
            }
            gsync(++ep);

            // ---- X phase m: gates, TD, BU = Wmid·TD, recon ----
            float td_val;
            {
                const int k = tid;
                float zi = ldf(&g_z[k]),          zf = ldf(&g_z[HH + k]);
                float zg = ldf(&g_z[2 * HH + k]), zo = ldf(&g_z[3 * HH + k]);
                float c_old = ldf(&g_c[p][m][k]);
                float cn = sigm(zf) * c_old + sigm(zi) * tanhf(zg);
                float hn = sigm(zo) * tanhf(cn);
                td_val = fabsf(hn - ldf(&g_reconR[m][k]));
                __half tdh = __float2half_rn(td_val);
                __half hnh = __float2half_rn(hn);
                sTDh[k] = tdh;
                shh[k]  = hnh;
                if (blockIdx.x == 0) {
                    stf(&g_c[1 - p][m][k], cn);
                    g_xin[m][HH + k]     = tdh;   // TD carry for next step
                    g_xin[m][2 * HH + k] = hnh;   // h carry for next step
                }
            }
            __syncthreads();
            const int nrec = (m == 0) ? CC : HH;
            if (gw < HH) {
                float a = warp_red(dot16<2048>(&h_Wmid[((size_t)m * HH + gw) * HH], sTDh, lane));
                __half r = __float2half_rn(a + Wmid_b[m * HH + gw]);
                if (lane == 0) { if (m < 3) g_xin[m + 1][gw] = r; else g_xtop[gw] = r; }
            } else if (gw < HH + nrec) {
                int r = gw - HH;
                if (m == 0) {
                    float a = warp_red(dot16<2048>(&h_V1[(size_t)r * HH], shh, lane));
                    if (lane == 0) stf(&g_recon1[r], a + V1_b[r]);
                } else {
                    float a = warp_red(dot16<2048>(&h_Vmid[((size_t)(m - 1) * HH + r) * HH], shh, lane));
                    if (lane == 0) stf(&g_reconR[m - 1][r], a + Vmid_b[(m - 1) * HH + r]);
                }
            }
            if (blockIdx.x == 0) {
                float s = block_sum(td_val, sred);
                if (tid == 0) stf(&g_loss_parts[t][1 + m], s);
            }
            gsync(++ep);
        }

        // ---- top LSTM phase: z = Wih_top·BU5 + Whh_top·h5_prev + b ----
        if (tid < 256)
            reinterpret_cast<uint4*>(sxh)[tid] =
                __ldcg(reinterpret_cast<const uint4*>(g_xtop) + tid);
        __syncthreads();
        if (gw < 4096) {
            float a = dot8<1024>(w8_Wih_top + (size_t)gw * 1024, sxh, lane)
                    + dot8<1024>(w8_Whh_top + (size_t)gw * 1024, sxh + HH, lane);
            a = warp_red(a);
            if (lane == 0) stf(&g_z[gw], a * INV_WSCALE + btop[gw]);
        }
        gsync(++ep);

        // ---- X5: top gates, recon_top = Vmid[3]·h5; fused TD0/BU1/loss0 for t+1 ----
        {
            const bool more = (t + 1 < TT);
            {
                const int k = tid;
                float zi = ldf(&g_z[k]),          zf = ldf(&g_z[HH + k]);
                float zg = ldf(&g_z[2 * HH + k]), zo = ldf(&g_z[3 * HH + k]);
                float c_old = ldf(&g_c[p][4][k]);
                float cn = sigm(zf) * c_old + sigm(zi) * tanhf(zg);
                float hn = sigm(zo) * tanhf(cn);
                __half hnh = __float2half_rn(hn);
                shh[k] = hnh;
                if (blockIdx.x == 0) {
                    stf(&g_c[1 - p][4][k], cn);
                    g_xtop[HH + k] = hnh;
                }
            }
            if (more && tid < CC)
                sxf[tid] = fabsf(x_seq[(t + 1) * CC + tid] - ldf(&g_recon1[tid]));
            __syncthreads();
            if (gw < HH) {
                float a = warp_red(dot16<2048>(&h_Vmid[((size_t)3 * HH + gw) * HH], shh, lane));
                if (lane == 0) stf(&g_reconR[3][gw], a + Vmid_b[3 * HH + gw]);
            } else if (more && gw < 2 * HH) {
                int r = gw - HH;
                float a = warp_red(dot56h(&h_W0[(size_t)r * CC], sxf, lane));
                if (lane == 0) g_xin[0][r] = __float2half_rn(a + W0_b[r]);
            }
            if (more && blockIdx.x == 0) {
                float s = block_sum((tid < CC) ? sxf[tid] : 0.f, sred);
                if (tid == 0) stf(&g_loss_parts[t + 1][0], s);
            }
            gsync(++ep);
        }
    }

    // ---- epilogue: deterministic loss reduction (all parts written by block 0) ----
    if (blockIdx.x == 0) {
        const float* parts = &g_loss_parts[0][0];
        float v = 0.f;
        for (int i = tid; i < TT * 5; i += NTHR) v += ldf(&parts[i]);
        float s = block_sum(v, sred);
        if (tid == 0) out[0] = s;
    }
}

// ---------------- launch ---------------------------------------------------------
extern "C" void kernel_launch(void* const* d_in, const int* in_sizes, int n_in,
                              void* d_out, int out_size) {
    (void)in_sizes; (void)n_in; (void)out_size;
    const float* x_seq  = (const float*)d_in[0];
    const float* W0_w   = (const float*)d_in[1];
    const float* W0_b   = (const float*)d_in[2];
    const float* Wmid_w = (const float*)d_in[3];
    const float* Wmid_b = (const float*)d_in[4];
    const float* V1_w   = (const float*)d_in[5];
    const float* V1_b   = (const float*)d_in[6];
    const float* Vmid_w = (const float*)d_in[7];
    const float* Vmid_b = (const float*)d_in[8];
    const float* Wihm   = (const float*)d_in[9];
    const float* Whhm   = (const float*)d_in[10];
    const float* bmid   = (const float*)d_in[11];
    const float* Wiht   = (const float*)d_in[12];
    const float* Whht   = (const float*)d_in[13];
    const float* btop   = (const float*)d_in[14];

    convert_kernel<<<2048, 256>>>(W0_w, Wmid_w, V1_w, Vmid_w, Wihm, Whhm, Wiht, Whht);
    predcells_kernel<<<NBLK, NTHR>>>(x_seq, W0_b, Wmid_b, V1_b, Vmid_b, bmid, btop,
                                     (float*)d_out);
}